// round 7
// baseline (speedup 1.0000x reference)
#include <cuda_runtime.h>
#include <cstdint>

#define BB 512
#define RR 264
#define KK 32
#define SS 9
#define KST 288            // sT k-row stride in floats (1152 B = 9 x 128B)
#define NTHREADS 256
#define NTASKS 35          // 32 core (4x8 cell blocks) + 3 border

typedef unsigned long long ull;

__device__ __constant__ int c_ends[SS]   = {28, 58, 92, 121, 150, 180, 210, 240, 264};
__device__ __constant__ int c_starts[SS] = {0, 28, 58, 92, 121, 150, 180, 210, 240};
__device__ __constant__ float c_sizes[SS] = {28.f, 30.f, 34.f, 29.f, 29.f, 30.f, 30.f, 30.f, 24.f};

__device__ __forceinline__ ull fma2(ull a, ull b, ull c) {
    ull d;
    asm("fma.rn.f32x2 %0, %1, %2, %3;" : "=l"(d) : "l"(a), "l"(b), "l"(c));
    return d;
}
__device__ __forceinline__ ull dup2(float x) {
    ull d;
    asm("mov.b64 %0, {%1, %1};" : "=l"(d) : "f"(x));
    return d;
}
__device__ __forceinline__ float2 unpack2(ull v) {
    float2 r;
    asm("mov.b64 {%0, %1}, %2;" : "=f"(r.x), "=f"(r.y) : "l"(v));
    return r;
}

extern "C" __global__ void __launch_bounds__(NTHREADS, 2)
gram_kernel(const float* __restrict__ E, float* __restrict__ out)
{
    float* intra = out;
    float* inter = out + (size_t)BB * RR * RR;
    float* adj   = inter + (size_t)BB * SS * SS;

    __shared__ float sT[KK * KST];   // E[b]^T : sT[k*KST + r]
    __shared__ int2  sLoHi[RR];      // per-row segment range [lo, hi)
    __shared__ float sSum[SS * KK];

    const int b   = blockIdx.x >> 1;
    const int cx  = blockIdx.x & 1;
    const int tid = threadIdx.x;
    const float* Eb = E + (size_t)b * (RR * KK);

    // ---- transpose-load E[b] into smem ----
    for (int i = tid; i < (RR * KK) / 4; i += NTHREADS) {
        float4 v = reinterpret_cast<const float4*>(Eb)[i];
        int row = i >> 3, k4 = (i & 7) << 2;
        sT[(k4 + 0) * KST + row] = v.x;
        sT[(k4 + 1) * KST + row] = v.y;
        sT[(k4 + 2) * KST + row] = v.z;
        sT[(k4 + 3) * KST + row] = v.w;
    }
    for (int r = tid; r < RR; r += NTHREADS) {
        int s = 0;
        #pragma unroll
        for (int j = 0; j < SS; j++) s += (r >= c_ends[j]) ? 1 : 0;
        sLoHi[r] = make_int2(c_starts[s], c_ends[s]);
    }
    __syncthreads();

    // ---- inter-network block means (cx==0 CTA of each batch) ----
    if (cx == 0) {
        for (int i = tid; i < SS * KK; i += NTHREADS) {
            int s  = i >> 5;
            int d  = i & 31;
            int st = (s == 0) ? 0 : c_ends[s - 1];
            int en = c_ends[s];
            float a = 0.0f;
            const float* kp = &sT[d * KST];
            for (int r = st; r < en; r++) a += kp[r];
            sSum[i] = a;
        }
        __syncthreads();
        if (tid < SS * SS) {
            int s = tid / SS, t = tid % SS;
            float a = 0.0f;
            #pragma unroll
            for (int d = 0; d < KK; d++)
                a += sSum[s * KK + d] * sSum[t * KK + d];
            inter[(size_t)b * SS * SS + tid] = a / (c_sizes[s] * c_sizes[t]);
        }
    }

    const int w    = tid >> 5;
    const int lane = tid & 31;
    const int t0   = cx ? 18 : 0;
    const int t1   = cx ? NTASKS : 18;

    for (int t = t0 + w; t < t1; t += 8) {
        // ---- cell mapping: core tasks are 4x8 lane blocks, border generic ----
        int ci, cj;
        bool valid;
        if (t < 32) {
            int br = t >> 2, bc = t & 3;          // 8x4 block grid over 32x32 cells
            ci = br * 4 + (lane >> 3);
            cj = bc * 8 + (lane & 7);
            valid = true;
        } else {
            int m = (t - 32) * 32 + lane;         // 65 border cells over 3 warps
            valid = (m < 65);
            int mm = valid ? m : 0;
            ci = (mm < 33) ? 32 : (mm - 33);
            cj = (mm < 33) ? mm : 32;
        }
        const int r0 = ci * 8;
        const int c0 = cj * 8;

        // acc[cjj][rp] = (out[r0+2rp][c0+cjj], out[r0+2rp+1][c0+cjj])
        ull acc[8][4];
        #pragma unroll
        for (int j = 0; j < 8; j++)
            #pragma unroll
            for (int p = 0; p < 4; p++) acc[j][p] = 0ull;

        #pragma unroll 4
        for (int k = 0; k < KK; k++) {
            const float* kp = &sT[k * KST];
            // a: 4 row-pairs (natural packed pairs, no dup needed)
            ulonglong2 a01 = *reinterpret_cast<const ulonglong2*>(kp + r0);
            ulonglong2 a23 = *reinterpret_cast<const ulonglong2*>(kp + r0 + 4);
            // b: 8 column scalars
            float4 b0 = *reinterpret_cast<const float4*>(kp + c0);
            float4 b1 = *reinterpret_cast<const float4*>(kp + c0 + 4);
            float bf[8] = {b0.x, b0.y, b0.z, b0.w, b1.x, b1.y, b1.z, b1.w};
            #pragma unroll
            for (int j = 0; j < 8; j++) {
                ull bd = dup2(bf[j]);
                acc[j][0] = fma2(a01.x, bd, acc[j][0]);
                acc[j][1] = fma2(a01.y, bd, acc[j][1]);
                acc[j][2] = fma2(a23.x, bd, acc[j][2]);
                acc[j][3] = fma2(a23.y, bd, acc[j][3]);
            }
        }

        if (valid) {
            float* abase = adj   + (((size_t)b * RR + r0) * RR) + c0;
            float* ibase = intra + (((size_t)b * RR + r0) * RR) + c0;
            #pragma unroll
            for (int p = 0; p < 4; p++) {
                float2 u[8];
                #pragma unroll
                for (int j = 0; j < 8; j++) u[j] = unpack2(acc[j][p]);
                // even row r0+2p
                float4 e0; e0.x = u[0].x; e0.y = u[1].x; e0.z = u[2].x; e0.w = u[3].x;
                float4 e1; e1.x = u[4].x; e1.y = u[5].x; e1.z = u[6].x; e1.w = u[7].x;
                // odd row r0+2p+1
                float4 o0; o0.x = u[0].y; o0.y = u[1].y; o0.z = u[2].y; o0.w = u[3].y;
                float4 o1; o1.x = u[4].y; o1.y = u[5].y; o1.z = u[6].y; o1.w = u[7].y;

                const int re = r0 + 2 * p;
                float* ae = abase + (size_t)(2 * p) * RR;
                float* ie = ibase + (size_t)(2 * p) * RR;
                *reinterpret_cast<float4*>(ae)          = e0;
                *reinterpret_cast<float4*>(ae + 4)      = e1;
                *reinterpret_cast<float4*>(ae + RR)     = o0;
                *reinterpret_cast<float4*>(ae + RR + 4) = o1;

                const int2 lhe = sLoHi[re];
                const int2 lho = sLoHi[re + 1];
                float4 we0, we1, wo0, wo1;
                we0.x = (c0 + 0 >= lhe.x && c0 + 0 < lhe.y) ? e0.x : 0.0f;
                we0.y = (c0 + 1 >= lhe.x && c0 + 1 < lhe.y) ? e0.y : 0.0f;
                we0.z = (c0 + 2 >= lhe.x && c0 + 2 < lhe.y) ? e0.z : 0.0f;
                we0.w = (c0 + 3 >= lhe.x && c0 + 3 < lhe.y) ? e0.w : 0.0f;
                we1.x = (c0 + 4 >= lhe.x && c0 + 4 < lhe.y) ? e1.x : 0.0f;
                we1.y = (c0 + 5 >= lhe.x && c0 + 5 < lhe.y) ? e1.y : 0.0f;
                we1.z = (c0 + 6 >= lhe.x && c0 + 6 < lhe.y) ? e1.z : 0.0f;
                we1.w = (c0 + 7 >= lhe.x && c0 + 7 < lhe.y) ? e1.w : 0.0f;
                wo0.x = (c0 + 0 >= lho.x && c0 + 0 < lho.y) ? o0.x : 0.0f;
                wo0.y = (c0 + 1 >= lho.x && c0 + 1 < lho.y) ? o0.y : 0.0f;
                wo0.z = (c0 + 2 >= lho.x && c0 + 2 < lho.y) ? o0.z : 0.0f;
                wo0.w = (c0 + 3 >= lho.x && c0 + 3 < lho.y) ? o0.w : 0.0f;
                wo1.x = (c0 + 4 >= lho.x && c0 + 4 < lho.y) ? o1.x : 0.0f;
                wo1.y = (c0 + 5 >= lho.x && c0 + 5 < lho.y) ? o1.y : 0.0f;
                wo1.z = (c0 + 6 >= lho.x && c0 + 6 < lho.y) ? o1.z : 0.0f;
                wo1.w = (c0 + 7 >= lho.x && c0 + 7 < lho.y) ? o1.w : 0.0f;
                *reinterpret_cast<float4*>(ie)          = we0;
                *reinterpret_cast<float4*>(ie + 4)      = we1;
                *reinterpret_cast<float4*>(ie + RR)     = wo0;
                *reinterpret_cast<float4*>(ie + RR + 4) = wo1;
            }
        }
    }
}

extern "C" void kernel_launch(void* const* d_in, const int* in_sizes, int n_in,
                              void* d_out, int out_size)
{
    (void)in_sizes; (void)n_in; (void)out_size;
    const float* E = (const float*)d_in[0];
    float* out = (float*)d_out;

    gram_kernel<<<2 * BB, NTHREADS>>>(E, out);
}

// round 9
// speedup vs baseline: 1.7421x; 1.7421x over previous
#include <cuda_runtime.h>
#include <cuda_bf16.h>
#include <cstdint>

#define BB 512
#define RR 264
#define KK 32
#define SS 9
#define NTHREADS 256
#define SROWB 144                 // operand row stride (bytes): conflict-free ldmatrix
#define NPAD 288                  // padded rows (264 real + zeros)
#define OPBYTES (NPAD * SROWB)    // 41472
#define SSTF 36                   // stage row stride (floats)
#define STAGEB (8 * 16 * SSTF * 4) // 18432
#define SMEM_TOTAL (OPBYTES + RR * 8 + SS * KK * 4 + STAGEB)  // 63168

__device__ __constant__ int   c_ends[SS]  = {28, 58, 92, 121, 150, 180, 210, 240, 264};
__device__ __constant__ float c_sizes[SS] = {28.f, 30.f, 34.f, 29.f, 29.f, 30.f, 30.f, 30.f, 24.f};

__device__ __forceinline__ uint32_t smem_u32(const void* p) {
    uint32_t a;
    asm("{ .reg .u64 t; cvta.to.shared.u64 t, %1; cvt.u32.u64 %0, t; }" : "=r"(a) : "l"(p));
    return a;
}
__device__ __forceinline__ void ldsm4(uint32_t* r, uint32_t addr) {
    asm volatile("ldmatrix.sync.aligned.m8n8.x4.shared.b16 {%0,%1,%2,%3}, [%4];"
        : "=r"(r[0]), "=r"(r[1]), "=r"(r[2]), "=r"(r[3]) : "r"(addr));
}
__device__ __forceinline__ void mma16816(float* d, const uint32_t* a, uint32_t b0, uint32_t b1) {
    asm volatile(
        "mma.sync.aligned.m16n8k16.row.col.f32.bf16.bf16.f32 "
        "{%0,%1,%2,%3}, {%4,%5,%6,%7}, {%8,%9}, {%0,%1,%2,%3};"
        : "+f"(d[0]), "+f"(d[1]), "+f"(d[2]), "+f"(d[3])
        : "r"(a[0]), "r"(a[1]), "r"(a[2]), "r"(a[3]), "r"(b0), "r"(b1));
}
__device__ __forceinline__ uint32_t packbf(float a, float b) {
    unsigned short ua = __bfloat16_as_ushort(__float2bfloat16(a));
    unsigned short ub = __bfloat16_as_ushort(__float2bfloat16(b));
    return (uint32_t)ua | ((uint32_t)ub << 16);
}

extern "C" __global__ void __launch_bounds__(NTHREADS, 3)
gram_mma(const float* __restrict__ E, float* __restrict__ out)
{
    float* intra = out;
    float* inter = out + (size_t)BB * RR * RR;
    float* adj   = inter + (size_t)BB * SS * SS;

    extern __shared__ unsigned char dyn[];
    unsigned char* sOp   = dyn;                                  // [NPAD][SROWB]: hi 64B | lo 64B
    int2*          sLoHi = (int2*)(dyn + OPBYTES);
    float*         sSum  = (float*)(dyn + OPBYTES + RR * 8);
    float*         sStg  = (float*)(dyn + OPBYTES + RR * 8 + SS * KK * 4);

    const int cr   = blockIdx.x;          // row-third: tiles {0-5, 6-11, 12-16}
    const int b    = blockIdx.y;
    const int tid  = threadIdx.x;
    const int wid  = tid >> 5;
    const int lane = tid & 31;
    const float* Eb = E + (size_t)b * (RR * KK);

    // ---- fp32 -> bf16 hi|lo split into smem; zero padded rows ----
    for (int r = tid; r < NPAD; r += NTHREADS) {
        unsigned char* dst = sOp + r * SROWB;
        if (r < RR) {
            const float4* src = reinterpret_cast<const float4*>(Eb + r * KK);
            uint32_t h[16], l[16];
            #pragma unroll
            for (int q = 0; q < 8; q++) {
                float4 v = src[q];
                uint32_t h01 = packbf(v.x, v.y);
                uint32_t h23 = packbf(v.z, v.w);
                float rx = v.x - __bfloat162float(__ushort_as_bfloat16((unsigned short)(h01 & 0xffff)));
                float ry = v.y - __bfloat162float(__ushort_as_bfloat16((unsigned short)(h01 >> 16)));
                float rz = v.z - __bfloat162float(__ushort_as_bfloat16((unsigned short)(h23 & 0xffff)));
                float rw = v.w - __bfloat162float(__ushort_as_bfloat16((unsigned short)(h23 >> 16)));
                h[2 * q] = h01; h[2 * q + 1] = h23;
                l[2 * q] = packbf(rx, ry); l[2 * q + 1] = packbf(rz, rw);
            }
            #pragma unroll
            for (int q = 0; q < 4; q++) {
                *reinterpret_cast<uint4*>(dst + 16 * q) =
                    make_uint4(h[4 * q], h[4 * q + 1], h[4 * q + 2], h[4 * q + 3]);
                *reinterpret_cast<uint4*>(dst + 64 + 16 * q) =
                    make_uint4(l[4 * q], l[4 * q + 1], l[4 * q + 2], l[4 * q + 3]);
            }
        } else {
            #pragma unroll
            for (int q = 0; q < 8; q++)
                *reinterpret_cast<uint4*>(dst + 16 * q) = make_uint4(0, 0, 0, 0);
        }
    }
    for (int r = tid; r < RR; r += NTHREADS) {
        int s = 0;
        #pragma unroll
        for (int j = 0; j < SS; j++) s += (r >= c_ends[j]) ? 1 : 0;
        int lo = (s == 0) ? 0 : c_ends[s - 1];
        sLoHi[r] = make_int2(lo, c_ends[s]);
    }
    if (cr == 0) {
        for (int i = tid; i < SS * KK; i += NTHREADS) {
            int s  = i >> 5;
            int d  = i & 31;
            int st = (s == 0) ? 0 : c_ends[s - 1];
            int en = c_ends[s];
            float a = 0.0f;
            for (int r = st; r < en; r++) a += Eb[r * KK + d];
            sSum[i] = a;
        }
    }
    __syncthreads();

    if (cr == 0 && tid < SS * SS) {
        int s = tid / SS, t = tid % SS;
        float a = 0.0f;
        #pragma unroll
        for (int d = 0; d < KK; d++)
            a += sSum[s * KK + d] * sSum[t * KK + d];
        inter[(size_t)b * SS * SS + tid] = a / (c_sizes[s] * c_sizes[t]);
    }

    // ---- warp tasks: 16x32 output tiles ----
    const uint32_t opBase = smem_u32(sOp);
    const int m8    = lane >> 3;
    const int rr8   = lane & 7;
    const int radd  = rr8 + ((m8 & 1) << 3);     // ldmatrix row-within-16
    const int kaddB = (m8 >> 1) << 4;            // +16B for k8..15 halves
    const int gid   = lane >> 2;
    const int tig   = lane & 3;
    const int ntasks = (cr == 2) ? 45 : 54;      // (#m16 tiles in this third) * 9
    float* stg = sStg + wid * (16 * SSTF);

    for (int t = wid; t < ntasks; t += 8) {
        const int mt    = t / 9;
        const int ns    = t - mt * 9;
        const int rbase = (cr * 6 + mt) * 16;
        const int c0    = ns * 32;

        // A fragments: 4 k-chunks (H0,H1,L0,L1 at byte cols 0,32,64,96)
        uint32_t a[4][4];
        {
            uint32_t aaddr = opBase + (uint32_t)(rbase + radd) * SROWB + kaddB;
            #pragma unroll
            for (int c = 0; c < 4; c++) ldsm4(a[c], aaddr + c * 32);
        }

        float d[4][4];
        #pragma unroll
        for (int j = 0; j < 4; j++)
            #pragma unroll
            for (int p = 0; p < 4; p++) d[j][p] = 0.0f;

        #pragma unroll
        for (int bc = 0; bc < 4; bc++) {
            uint32_t bg0[4], bg1[4];
            uint32_t baddr = opBase + (uint32_t)(c0 + radd) * SROWB + kaddB + bc * 32;
            ldsm4(bg0, baddr);
            ldsm4(bg1, baddr + 16 * SROWB);
            // partners: bc in {H0,H1}: a = {same-H, same-L}; bc in {L0,L1}: a = {H same k-chunk}
            const int ac1 = (bc < 2) ? bc : (bc - 2);
            mma16816(d[0], a[ac1], bg0[0], bg0[2]);
            mma16816(d[1], a[ac1], bg0[1], bg0[3]);
            mma16816(d[2], a[ac1], bg1[0], bg1[2]);
            mma16816(d[3], a[ac1], bg1[1], bg1[3]);
            if (bc < 2) {
                mma16816(d[0], a[bc + 2], bg0[0], bg0[2]);
                mma16816(d[1], a[bc + 2], bg0[1], bg0[3]);
                mma16816(d[2], a[bc + 2], bg1[0], bg1[2]);
                mma16816(d[3], a[bc + 2], bg1[1], bg1[3]);
            }
        }

        // ---- stage fragments to smem, then coalesced 128B-row stores ----
        #pragma unroll
        for (int j = 0; j < 4; j++) {
            stg[gid * SSTF + 8 * j + 2 * tig]           = d[j][0];
            stg[gid * SSTF + 8 * j + 2 * tig + 1]       = d[j][1];
            stg[(gid + 8) * SSTF + 8 * j + 2 * tig]     = d[j][2];
            stg[(gid + 8) * SSTF + 8 * j + 2 * tig + 1] = d[j][3];
        }
        __syncwarp();
        #pragma unroll
        for (int i = 0; i < 4; i++) {
            const int f  = i * 32 + lane;
            const int rl = f >> 3;
            const int q  = f & 7;
            const int rg = rbase + rl;
            const int cg = c0 + 4 * q;
            if (rg < RR && cg < RR) {
                float4 v = *reinterpret_cast<float4*>(stg + rl * SSTF + 4 * q);
                const size_t off = ((size_t)b * RR + rg) * RR + cg;
                *reinterpret_cast<float4*>(adj + off) = v;
                int2 lh = sLoHi[rg];
                float4 w;
                w.x = (cg + 0 >= lh.x && cg + 0 < lh.y) ? v.x : 0.0f;
                w.y = (cg + 1 >= lh.x && cg + 1 < lh.y) ? v.y : 0.0f;
                w.z = (cg + 2 >= lh.x && cg + 2 < lh.y) ? v.z : 0.0f;
                w.w = (cg + 3 >= lh.x && cg + 3 < lh.y) ? v.w : 0.0f;
                *reinterpret_cast<float4*>(intra + off) = w;
            }
        }
        __syncwarp();
    }
}

extern "C" void kernel_launch(void* const* d_in, const int* in_sizes, int n_in,
                              void* d_out, int out_size)
{
    (void)in_sizes; (void)n_in; (void)out_size;
    const float* E = (const float*)d_in[0];
    float* out = (float*)d_out;

    cudaFuncSetAttribute(gram_mma, cudaFuncAttributeMaxDynamicSharedMemorySize, SMEM_TOTAL);
    dim3 grid(3, BB);
    gram_mma<<<grid, NTHREADS, SMEM_TOTAL>>>(E, out);
}

// round 10
// speedup vs baseline: 2.0508x; 1.1772x over previous
#include <cuda_runtime.h>
#include <cuda_bf16.h>
#include <cstdint>

#define BB 512
#define RR 264
#define KK 32
#define SS 9
#define NTHREADS 256
#define SROWB 144                  // operand row stride (bytes), conflict-free ldmatrix
#define NPAD 288                   // padded rows
#define OPBYTES (NPAD * SROWB)     // 41472
#define SSTF 40                    // stage row stride (floats) -> conflict-free STS.64
#define STAGEB (8 * 32 * SSTF * 4) // 40960
#define SMEM_TOTAL (OPBYTES + RR * 8 + SS * KK * 4 + STAGEB)

__device__ __constant__ int   c_ends[SS]  = {28, 58, 92, 121, 150, 180, 210, 240, 264};
__device__ __constant__ float c_sizes[SS] = {28.f, 30.f, 34.f, 29.f, 29.f, 30.f, 30.f, 30.f, 24.f};

__device__ __forceinline__ uint32_t smem_u32(const void* p) {
    uint32_t a;
    asm("{ .reg .u64 t; cvta.to.shared.u64 t, %1; cvt.u32.u64 %0, t; }" : "=r"(a) : "l"(p));
    return a;
}
__device__ __forceinline__ void ldsm4(uint32_t* r, uint32_t addr) {
    asm volatile("ldmatrix.sync.aligned.m8n8.x4.shared.b16 {%0,%1,%2,%3}, [%4];"
        : "=r"(r[0]), "=r"(r[1]), "=r"(r[2]), "=r"(r[3]) : "r"(addr));
}
__device__ __forceinline__ void mma16816(float* d, const uint32_t* a, uint32_t b0, uint32_t b1) {
    asm volatile(
        "mma.sync.aligned.m16n8k16.row.col.f32.bf16.bf16.f32 "
        "{%0,%1,%2,%3}, {%4,%5,%6,%7}, {%8,%9}, {%0,%1,%2,%3};"
        : "+f"(d[0]), "+f"(d[1]), "+f"(d[2]), "+f"(d[3])
        : "r"(a[0]), "r"(a[1]), "r"(a[2]), "r"(a[3]), "r"(b0), "r"(b1));
}
__device__ __forceinline__ uint32_t packbf(float a, float b) {
    unsigned short ua = __bfloat16_as_ushort(__float2bfloat16(a));
    unsigned short ub = __bfloat16_as_ushort(__float2bfloat16(b));
    return (uint32_t)ua | ((uint32_t)ub << 16);
}

extern "C" __global__ void __launch_bounds__(NTHREADS, 2)
gram_mma(const float* __restrict__ E, float* __restrict__ out)
{
    float* intra = out;
    float* inter = out + (size_t)BB * RR * RR;
    float* adj   = inter + (size_t)BB * SS * SS;

    extern __shared__ unsigned char dyn[];
    unsigned char* sOp   = dyn;                                  // [NPAD][SROWB]: hi 64B | lo 64B
    int2*          sLoHi = (int2*)(dyn + OPBYTES);
    float*         sSum  = (float*)(dyn + OPBYTES + RR * 8);
    float*         sStg  = (float*)(dyn + OPBYTES + RR * 8 + SS * KK * 4);

    const int b    = blockIdx.x;
    const int tid  = threadIdx.x;
    const int wid  = tid >> 5;
    const int lane = tid & 31;
    const float* Eb = E + (size_t)b * (RR * KK);

    // ---- fp32 -> bf16 hi|lo split into smem; zero padded rows ----
    for (int r = tid; r < NPAD; r += NTHREADS) {
        unsigned char* dst = sOp + r * SROWB;
        if (r < RR) {
            const float4* src = reinterpret_cast<const float4*>(Eb + r * KK);
            uint32_t h[16], l[16];
            #pragma unroll
            for (int q = 0; q < 8; q++) {
                float4 v = src[q];
                uint32_t h01 = packbf(v.x, v.y);
                uint32_t h23 = packbf(v.z, v.w);
                float rx = v.x - __bfloat162float(__ushort_as_bfloat16((unsigned short)(h01 & 0xffff)));
                float ry = v.y - __bfloat162float(__ushort_as_bfloat16((unsigned short)(h01 >> 16)));
                float rz = v.z - __bfloat162float(__ushort_as_bfloat16((unsigned short)(h23 & 0xffff)));
                float rw = v.w - __bfloat162float(__ushort_as_bfloat16((unsigned short)(h23 >> 16)));
                h[2 * q] = h01; h[2 * q + 1] = h23;
                l[2 * q] = packbf(rx, ry); l[2 * q + 1] = packbf(rz, rw);
            }
            #pragma unroll
            for (int q = 0; q < 4; q++) {
                *reinterpret_cast<uint4*>(dst + 16 * q) =
                    make_uint4(h[4 * q], h[4 * q + 1], h[4 * q + 2], h[4 * q + 3]);
                *reinterpret_cast<uint4*>(dst + 64 + 16 * q) =
                    make_uint4(l[4 * q], l[4 * q + 1], l[4 * q + 2], l[4 * q + 3]);
            }
        } else {
            #pragma unroll
            for (int q = 0; q < 8; q++)
                *reinterpret_cast<uint4*>(dst + 16 * q) = make_uint4(0, 0, 0, 0);
        }
    }
    for (int r = tid; r < RR; r += NTHREADS) {
        int s = 0;
        #pragma unroll
        for (int j = 0; j < SS; j++) s += (r >= c_ends[j]) ? 1 : 0;
        int lo = (s == 0) ? 0 : c_ends[s - 1];
        sLoHi[r] = make_int2(lo, c_ends[s]);
    }
    for (int i = tid; i < SS * KK; i += NTHREADS) {
        int s  = i >> 5;
        int d  = i & 31;
        int st = (s == 0) ? 0 : c_ends[s - 1];
        int en = c_ends[s];
        float a = 0.0f;
        for (int r = st; r < en; r++) a += Eb[r * KK + d];
        sSum[i] = a;
    }
    __syncthreads();

    if (tid < SS * SS) {
        int s = tid / SS, t = tid % SS;
        float a = 0.0f;
        #pragma unroll
        for (int d = 0; d < KK; d++)
            a += sSum[s * KK + d] * sSum[t * KK + d];
        inter[(size_t)b * SS * SS + tid] = a / (c_sizes[s] * c_sizes[t]);
    }

    // ---- warp tasks: 32x32 output tiles (9x9 task grid over padded 288) ----
    const uint32_t opBase = smem_u32(sOp);
    const int m8    = lane >> 3;
    const int rr8   = lane & 7;
    const int radd  = rr8 + ((m8 & 1) << 3);     // ldmatrix row-within-16
    const int kaddB = (m8 >> 1) << 4;            // +16B for k8..15 halves
    const int gid   = lane >> 2;
    const int tig   = lane & 3;
    float* stg = sStg + wid * (32 * SSTF);

    for (int t = wid; t < 81; t += 8) {
        const int mt    = t / 9;
        const int ns    = t - mt * 9;
        const int rbase = mt * 32;
        const int c0    = ns * 32;

        // A fragments: 2 m16 tiles x 4 k-chunks (H0,H1,L0,L1)
        uint32_t a[2][4][4];
        #pragma unroll
        for (int mi = 0; mi < 2; mi++) {
            uint32_t aaddr = opBase + (uint32_t)(rbase + 16 * mi + radd) * SROWB + kaddB;
            #pragma unroll
            for (int c = 0; c < 4; c++) ldsm4(a[mi][c], aaddr + c * 32);
        }

        float d[2][4][4];
        #pragma unroll
        for (int mi = 0; mi < 2; mi++)
            #pragma unroll
            for (int nj = 0; nj < 4; nj++)
                #pragma unroll
                for (int p = 0; p < 4; p++) d[mi][nj][p] = 0.0f;

        #pragma unroll
        for (int bc = 0; bc < 4; bc++) {
            uint32_t bg[2][4];
            uint32_t baddr = opBase + (uint32_t)(c0 + radd) * SROWB + kaddB + bc * 32;
            ldsm4(bg[0], baddr);
            ldsm4(bg[1], baddr + 16 * SROWB);
            const int ac1 = (bc < 2) ? bc : (bc - 2);
            #pragma unroll
            for (int mi = 0; mi < 2; mi++) {
                #pragma unroll
                for (int nh = 0; nh < 2; nh++) {
                    mma16816(d[mi][2 * nh],     a[mi][ac1], bg[nh][0], bg[nh][2]);
                    mma16816(d[mi][2 * nh + 1], a[mi][ac1], bg[nh][1], bg[nh][3]);
                    if (bc < 2) {
                        mma16816(d[mi][2 * nh],     a[mi][bc + 2], bg[nh][0], bg[nh][2]);
                        mma16816(d[mi][2 * nh + 1], a[mi][bc + 2], bg[nh][1], bg[nh][3]);
                    }
                }
            }
        }

        // ---- stage fragments (conflict-free STS.64), then coalesced stores ----
        #pragma unroll
        for (int mi = 0; mi < 2; mi++) {
            #pragma unroll
            for (int nj = 0; nj < 4; nj++) {
                float2 v0; v0.x = d[mi][nj][0]; v0.y = d[mi][nj][1];
                float2 v1; v1.x = d[mi][nj][2]; v1.y = d[mi][nj][3];
                const int cc = nj * 8 + 2 * tig;
                *reinterpret_cast<float2*>(stg + (mi * 16 + gid) * SSTF + cc)     = v0;
                *reinterpret_cast<float2*>(stg + (mi * 16 + gid + 8) * SSTF + cc) = v1;
            }
        }
        __syncwarp();
        #pragma unroll
        for (int i = 0; i < 8; i++) {
            const int f  = i * 32 + lane;
            const int rl = f >> 3;
            const int q  = f & 7;
            const int rg = rbase + rl;
            const int cg = c0 + 4 * q;
            if (rg < RR && cg < RR) {
                float4 v = *reinterpret_cast<float4*>(stg + rl * SSTF + 4 * q);
                const size_t off = ((size_t)b * RR + rg) * RR + cg;
                *reinterpret_cast<float4*>(adj + off) = v;
                int2 lh = sLoHi[rg];
                float4 w;
                w.x = (cg + 0 >= lh.x && cg + 0 < lh.y) ? v.x : 0.0f;
                w.y = (cg + 1 >= lh.x && cg + 1 < lh.y) ? v.y : 0.0f;
                w.z = (cg + 2 >= lh.x && cg + 2 < lh.y) ? v.z : 0.0f;
                w.w = (cg + 3 >= lh.x && cg + 3 < lh.y) ? v.w : 0.0f;
                *reinterpret_cast<float4*>(intra + off) = w;
            }
        }
        __syncwarp();
    }
}

extern "C" void kernel_launch(void* const* d_in, const int* in_sizes, int n_in,
                              void* d_out, int out_size)
{
    (void)in_sizes; (void)n_in; (void)out_size;
    const float* E = (const float*)d_in[0];
    float* out = (float*)d_out;

    cudaFuncSetAttribute(gram_mma, cudaFuncAttributeMaxDynamicSharedMemorySize, SMEM_TOTAL);
    gram_mma<<<BB, NTHREADS, SMEM_TOTAL>>>(E, out);
}